// round 1
// baseline (speedup 1.0000x reference)
#include <cuda_runtime.h>
#include <math.h>

#define DD  96
#define PLN (DD*DD)
#define VOL (DD*DD*DD)
#define NC  16

// Scratch (allocation-free): ping buffer A, scratch B, alive0 field, reduction scalars.
__device__ float    g_A[NC*VOL];
__device__ float    g_B[NC*VOL];
__device__ float    g_alive0[VOL];
__device__ unsigned g_maxPre[5];   // pre-update global max of ch3 per step (+1 spare)
__device__ unsigned g_maxPost[4];  // post-update global max of ch3 per step

// Monotonic float<->uint encoding for atomicMax on floats (handles negatives).
__device__ __forceinline__ unsigned encf(float f) {
    unsigned u = __float_as_uint(f);
    return (u & 0x80000000u) ? ~u : (u | 0x80000000u);
}
__device__ __forceinline__ float decf(unsigned e) {
    return __uint_as_float((e & 0x80000000u) ? (e ^ 0x80000000u) : ~e);
}

__global__ void init_kernel() {
    int t = threadIdx.x;
    if (t < 5) g_maxPre[t]  = 0x007FFFFFu;  // enc(-inf)
    if (t < 4) g_maxPost[t] = 0x007FFFFFu;
}

// Global max of the input's channel-3 field -> g_maxPre[0]
__global__ void reduce_ch3_kernel(const float* __restrict__ p) {
    float m = -INFINITY;
    for (int i = blockIdx.x * blockDim.x + threadIdx.x; i < VOL; i += gridDim.x * blockDim.x)
        m = fmaxf(m, p[i]);
    #pragma unroll
    for (int s = 16; s > 0; s >>= 1) m = fmaxf(m, __shfl_xor_sync(0xffffffffu, m, s));
    __shared__ float sm[8];
    if ((threadIdx.x & 31) == 0) sm[threadIdx.x >> 5] = m;
    __syncthreads();
    if (threadIdx.x == 0) {
        int nw = (blockDim.x + 31) / 32;
        float mm = sm[0];
        for (int i = 1; i < nw; i++) mm = fmaxf(mm, sm[i]);
        atomicMax(&g_maxPre[0], encf(mm));
    }
}

// Main compute: depthwise 3x3x3 conv (groups=16, mult=3) -> tanh(pw 48->64) ->
// tanh(pw 64->64) -> pw 64->16 -> residual. Also records alive0 = pool27(ch3 of cur)
// and reduces global max of new ch3 into g_maxPost[step].
__global__ __launch_bounds__(96) void update_kernel(
    const float* __restrict__ xin,
    const float* __restrict__ w_perc, const float* __restrict__ b_perc,
    const float* __restrict__ w1, const float* __restrict__ b1,
    const float* __restrict__ w2, const float* __restrict__ b2,
    const float* __restrict__ w3, const float* __restrict__ b3,
    int step)
{
    const float* cur = (step == 0) ? xin : (const float*)g_A;

    // Transposed weights in shared so inner loops do float4 broadcast LDS.128.
    __shared__ float s_wp[16*27*4];   // [(c*27+k)*4 + j], j = output within group (pad 4)
    __shared__ float s_bp[48];
    __shared__ float s_w1t[48*64];    // [i*64 + o]
    __shared__ float s_b1[64];
    __shared__ float s_w2t[64*64];    // [i*64 + o]
    __shared__ float s_b2[64];
    __shared__ float s_w3t[64*16];    // [i*16 + o]
    __shared__ float s_b3[16];
    __shared__ float s_wmax[3];

    int tid = threadIdx.x;
    for (int idx = tid; idx < 48*27; idx += 96) {
        int o = idx / 27, k = idx % 27;
        s_wp[((o/3)*27 + k)*4 + (o%3)] = w_perc[idx];
    }
    for (int idx = tid; idx < 48*64; idx += 96) { int o = idx/48, i = idx%48; s_w1t[i*64 + o] = w1[idx]; }
    for (int idx = tid; idx < 64*64; idx += 96) { int o = idx/64, i = idx%64; s_w2t[i*64 + o] = w2[idx]; }
    for (int idx = tid; idx < 16*64; idx += 96) { int o = idx/64, i = idx%64; s_w3t[i*16 + o] = w3[idx]; }
    if (tid < 48) s_bp[tid] = b_perc[tid];
    if (tid < 64) { s_b1[tid] = b1[tid]; s_b2[tid] = b2[tid]; }
    if (tid < 16) s_b3[tid] = b3[tid];
    __syncthreads();

    int w = tid, h = blockIdx.x, d = blockIdx.y;
    int pos = d*PLN + h*DD + w;
    bool vD[3] = { d > 0, true, d < DD-1 };
    bool vH[3] = { h > 0, true, h < DD-1 };
    bool vW[3] = { w > 0, true, w < DD-1 };

    float acc[48];
    #pragma unroll
    for (int o = 0; o < 48; o++) acc[o] = s_bp[o];
    float xc[NC];
    float alive0v = -INFINITY;

    #pragma unroll
    for (int c = 0; c < NC; c++) {
        const float* base = cur + c*VOL + pos;
        float n[27];
        #pragma unroll
        for (int kd = 0; kd < 3; kd++)
            #pragma unroll
            for (int kh = 0; kh < 3; kh++)
                #pragma unroll
                for (int kw = 0; kw < 3; kw++) {
                    int k = (kd*3 + kh)*3 + kw;
                    bool v = vD[kd] && vH[kh] && vW[kw];
                    float val = v ? base[(kd-1)*PLN + (kh-1)*DD + (kw-1)] : 0.0f;  // conv pads 0
                    n[k] = val;
                    if (c == 3) alive0v = v ? fmaxf(alive0v, val) : alive0v;       // pool pads -inf
                }
        xc[c] = n[13];
        #pragma unroll
        for (int k = 0; k < 27; k++) {
            float4 wv = *reinterpret_cast<const float4*>(&s_wp[(c*27 + k)*4]);
            acc[c*3+0] = fmaf(n[k], wv.x, acc[c*3+0]);
            acc[c*3+1] = fmaf(n[k], wv.y, acc[c*3+1]);
            acc[c*3+2] = fmaf(n[k], wv.z, acc[c*3+2]);
        }
    }

    float h1[64];
    #pragma unroll
    for (int o = 0; o < 64; o++) h1[o] = s_b1[o];
    #pragma unroll
    for (int i = 0; i < 48; i++) {
        float a = acc[i];
        #pragma unroll
        for (int o = 0; o < 64; o += 4) {
            float4 wv = *reinterpret_cast<const float4*>(&s_w1t[i*64 + o]);
            h1[o+0] = fmaf(a, wv.x, h1[o+0]); h1[o+1] = fmaf(a, wv.y, h1[o+1]);
            h1[o+2] = fmaf(a, wv.z, h1[o+2]); h1[o+3] = fmaf(a, wv.w, h1[o+3]);
        }
    }
    #pragma unroll
    for (int o = 0; o < 64; o++) h1[o] = tanhf(h1[o]);

    float h2[64];
    #pragma unroll
    for (int o = 0; o < 64; o++) h2[o] = s_b2[o];
    #pragma unroll
    for (int i = 0; i < 64; i++) {
        float a = h1[i];
        #pragma unroll
        for (int o = 0; o < 64; o += 4) {
            float4 wv = *reinterpret_cast<const float4*>(&s_w2t[i*64 + o]);
            h2[o+0] = fmaf(a, wv.x, h2[o+0]); h2[o+1] = fmaf(a, wv.y, h2[o+1]);
            h2[o+2] = fmaf(a, wv.z, h2[o+2]); h2[o+3] = fmaf(a, wv.w, h2[o+3]);
        }
    }
    #pragma unroll
    for (int o = 0; o < 64; o++) h2[o] = tanhf(h2[o]);

    float y[16];
    #pragma unroll
    for (int o = 0; o < 16; o++) y[o] = s_b3[o];
    #pragma unroll
    for (int i = 0; i < 64; i++) {
        float a = h2[i];
        #pragma unroll
        for (int o = 0; o < 16; o += 4) {
            float4 wv = *reinterpret_cast<const float4*>(&s_w3t[i*16 + o]);
            y[o+0] = fmaf(a, wv.x, y[o+0]); y[o+1] = fmaf(a, wv.y, y[o+1]);
            y[o+2] = fmaf(a, wv.z, y[o+2]); y[o+3] = fmaf(a, wv.w, y[o+3]);
        }
    }

    float xn3 = 0.0f;
    #pragma unroll
    for (int c = 0; c < NC; c++) {
        float v = xc[c] + y[c];
        g_B[c*VOL + pos] = v;
        if (c == 3) xn3 = v;
    }
    g_alive0[pos] = alive0v;

    // fused global-max of new ch3 (max(pool(f)) == max(f))
    float m = xn3;
    #pragma unroll
    for (int s = 16; s > 0; s >>= 1) m = fmaxf(m, __shfl_xor_sync(0xffffffffu, m, s));
    if ((tid & 31) == 0) s_wmax[tid >> 5] = m;
    __syncthreads();
    if (tid == 0) {
        float mm = fmaxf(fmaxf(s_wmax[0], s_wmax[1]), s_wmax[2]);
        atomicMax(&g_maxPost[step], encf(mm));
    }
}

// Masking + zero-slice; also reduces next step's pre-update global max of ch3.
__global__ __launch_bounds__(96) void finalize_kernel(
    float* __restrict__ out, int step, const int* __restrict__ pInOut)
{
    float* dst = (step == 3) ? out : (float*)g_A;

    int w = threadIdx.x, h = blockIdx.x, d = blockIdx.y;
    int pos = d*PLN + h*DD + w;

    bool vD[3] = { d > 0, true, d < DD-1 };
    bool vH[3] = { h > 0, true, h < DD-1 };
    bool vW[3] = { w > 0, true, w < DD-1 };
    const float* B3 = g_B + 3*VOL + pos;
    float m1 = -INFINITY;
    #pragma unroll
    for (int kd = 0; kd < 3; kd++)
        #pragma unroll
        for (int kh = 0; kh < 3; kh++)
            #pragma unroll
            for (int kw = 0; kw < 3; kw++)
                if (vD[kd] && vH[kh] && vW[kw])
                    m1 = fmaxf(m1, B3[(kd-1)*PLN + (kh-1)*DD + (kw-1)]);

    float th0 = 0.1f * decf(g_maxPre[step]);  if (isnan(th0)) th0 = -INFINITY;
    float th1 = 0.1f * decf(g_maxPost[step]); if (isnan(th1)) th1 = -INFINITY;
    bool life = (g_alive0[pos] > th0) && (m1 > th1);
    float lf = life ? 1.0f : 0.0f;
    bool zero = (d == DD-1) && (h >= *pInOut);

    float v3 = 0.0f;
    #pragma unroll
    for (int c = 0; c < NC; c++) {
        float v = g_B[c*VOL + pos] * lf;
        if (zero) v = 0.0f;
        dst[c*VOL + pos] = v;
        if (c == 3) v3 = v;
    }

    float m = v3;
    #pragma unroll
    for (int s = 16; s > 0; s >>= 1) m = fmaxf(m, __shfl_xor_sync(0xffffffffu, m, s));
    __shared__ float s_wmax[3];
    if ((threadIdx.x & 31) == 0) s_wmax[threadIdx.x >> 5] = m;
    __syncthreads();
    if (threadIdx.x == 0) {
        float mm = fmaxf(fmaxf(s_wmax[0], s_wmax[1]), s_wmax[2]);
        atomicMax(&g_maxPre[step + 1], encf(mm));
    }
}

extern "C" void kernel_launch(void* const* d_in, const int* in_sizes, int n_in,
                              void* d_out, int out_size) {
    (void)in_sizes; (void)n_in; (void)out_size;
    const float* x      = (const float*)d_in[0];
    const float* w_perc = (const float*)d_in[1];
    const float* b_perc = (const float*)d_in[2];
    const float* w1     = (const float*)d_in[3];
    const float* b1     = (const float*)d_in[4];
    const float* w2     = (const float*)d_in[5];
    const float* b2     = (const float*)d_in[6];
    const float* w3     = (const float*)d_in[7];
    const float* b3     = (const float*)d_in[8];
    const int*   pInOut = (const int*)d_in[12];
    float* out = (float*)d_out;

    init_kernel<<<1, 32>>>();
    reduce_ch3_kernel<<<432, 256>>>(x + 3*VOL);

    dim3 grd(DD, DD);
    for (int s = 0; s < 4; s++) {
        update_kernel<<<grd, 96>>>(x, w_perc, b_perc, w1, b1, w2, b2, w3, b3, s);
        finalize_kernel<<<grd, 96>>>(out, s, pInOut);
    }
}

// round 2
// speedup vs baseline: 1.9282x; 1.9282x over previous
#include <cuda_runtime.h>
#include <math.h>

#define DD  96
#define PLN (DD*DD)
#define VOL (DD*DD*DD)
#define NC  16

// Scratch (allocation-free): ping buffer A, scratch B, alive0 field, reduction scalars.
__device__ float    g_A[NC*VOL];
__device__ float    g_B[NC*VOL];
__device__ float    g_alive0[VOL];
__device__ unsigned g_maxPre[5];   // pre-update global max of ch3 per step (+1 spare)
__device__ unsigned g_maxPost[4];  // post-update global max of ch3 per step

// Monotonic float<->uint encoding for atomicMax on floats (handles negatives).
__device__ __forceinline__ unsigned encf(float f) {
    unsigned u = __float_as_uint(f);
    return (u & 0x80000000u) ? ~u : (u | 0x80000000u);
}
__device__ __forceinline__ float decf(unsigned e) {
    return __uint_as_float((e & 0x80000000u) ? (e ^ 0x80000000u) : ~e);
}

__device__ __forceinline__ float tanh_fast(float x) {
    float y;
    asm("tanh.approx.f32 %0, %1;" : "=f"(y) : "f"(x));
    return y;
}

__global__ void init_kernel() {
    int t = threadIdx.x;
    if (t < 5) g_maxPre[t]  = 0x007FFFFFu;  // enc(-inf)
    if (t < 4) g_maxPost[t] = 0x007FFFFFu;
}

// Global max of the input's channel-3 field -> g_maxPre[0]
__global__ void reduce_ch3_kernel(const float* __restrict__ p) {
    float m = -INFINITY;
    for (int i = blockIdx.x * blockDim.x + threadIdx.x; i < VOL; i += gridDim.x * blockDim.x)
        m = fmaxf(m, p[i]);
    #pragma unroll
    for (int s = 16; s > 0; s >>= 1) m = fmaxf(m, __shfl_xor_sync(0xffffffffu, m, s));
    __shared__ float sm[8];
    if ((threadIdx.x & 31) == 0) sm[threadIdx.x >> 5] = m;
    __syncthreads();
    if (threadIdx.x == 0) {
        int nw = (blockDim.x + 31) / 32;
        float mm = sm[0];
        for (int i = 1; i < nw; i++) mm = fmaxf(mm, sm[i]);
        atomicMax(&g_maxPre[0], encf(mm));
    }
}

// Main compute: depthwise 3x3x3 conv (groups=16, mult=3) -> tanh(pw 48->64) ->
// tanh(pw 64->64) -> pw 64->16 -> residual. Also records alive0 = pool27(ch3 of cur)
// and reduces global max of new ch3 into g_maxPost[step].
// Block (96,2): tx=w, ty=h_sub. Grid (48, 96): bx covers h pairs, by=d.
__global__ __launch_bounds__(192, 2) void update_kernel(
    const float* __restrict__ xin,
    const float* __restrict__ w_perc, const float* __restrict__ b_perc,
    const float* __restrict__ w1, const float* __restrict__ b1,
    const float* __restrict__ w2, const float* __restrict__ b2,
    const float* __restrict__ w3, const float* __restrict__ b3,
    int step)
{
    const float* cur = (step == 0) ? xin : (const float*)g_A;

    // Transposed weights in shared so inner loops do float4 broadcast LDS.128.
    __shared__ float s_wp[16*27*4];   // [(c*27+k)*4 + j], j = output within group (pad 4)
    __shared__ float s_bp[48];
    __shared__ float s_w1t[48*64];    // [i*64 + o]
    __shared__ float s_b1[64];
    __shared__ float s_w2t[64*64];    // [i*64 + o]
    __shared__ float s_b2[64];
    __shared__ float s_w3t[64*16];    // [i*16 + o]
    __shared__ float s_b3[16];
    __shared__ float s_wmax[6];

    int tid = threadIdx.y * 96 + threadIdx.x;
    for (int idx = tid; idx < 48*27; idx += 192) {
        int o = idx / 27, k = idx % 27;
        s_wp[((o/3)*27 + k)*4 + (o%3)] = w_perc[idx];
    }
    for (int idx = tid; idx < 48*64; idx += 192) { int o = idx/48, i = idx%48; s_w1t[i*64 + o] = w1[idx]; }
    for (int idx = tid; idx < 64*64; idx += 192) { int o = idx/64, i = idx%64; s_w2t[i*64 + o] = w2[idx]; }
    for (int idx = tid; idx < 16*64; idx += 192) { int o = idx/64, i = idx%64; s_w3t[i*16 + o] = w3[idx]; }
    if (tid < 48) s_bp[tid] = b_perc[tid];
    if (tid < 64) { s_b1[tid] = b1[tid]; s_b2[tid] = b2[tid]; }
    if (tid < 16) s_b3[tid] = b3[tid];
    __syncthreads();

    int w = threadIdx.x;
    int h = blockIdx.x * 2 + threadIdx.y;
    int d = blockIdx.y;
    int pos = d*PLN + h*DD + w;
    bool vD[3] = { d > 0, true, d < DD-1 };
    bool vH[3] = { h > 0, true, h < DD-1 };
    bool vW[3] = { w > 0, true, w < DD-1 };

    // ---- depthwise conv (streamed neighborhood, no n[] array) ----
    float f[48];
    #pragma unroll
    for (int o = 0; o < 48; o++) f[o] = s_bp[o];
    float alive0v = -INFINITY;

    #pragma unroll
    for (int c = 0; c < NC; c++) {
        const float* base = cur + c*VOL + pos;
        #pragma unroll
        for (int kd = 0; kd < 3; kd++)
            #pragma unroll
            for (int kh = 0; kh < 3; kh++)
                #pragma unroll
                for (int kw = 0; kw < 3; kw++) {
                    int k = (kd*3 + kh)*3 + kw;
                    bool v = vD[kd] && vH[kh] && vW[kw];
                    float val = v ? base[(kd-1)*PLN + (kh-1)*DD + (kw-1)] : 0.0f;  // conv pads 0
                    if (c == 3 && v) alive0v = fmaxf(alive0v, val);                // pool pads -inf
                    float4 wv = *reinterpret_cast<const float4*>(&s_wp[(c*27 + k)*4]);
                    f[c*3+0] = fmaf(val, wv.x, f[c*3+0]);
                    f[c*3+1] = fmaf(val, wv.y, f[c*3+1]);
                    f[c*3+2] = fmaf(val, wv.z, f[c*3+2]);
                }
    }

    // ---- layer 1: 48 -> 64, tanh ----
    float h1[64];
    #pragma unroll
    for (int o = 0; o < 64; o++) h1[o] = s_b1[o];
    #pragma unroll
    for (int i = 0; i < 48; i++) {
        float a = f[i];
        #pragma unroll
        for (int o = 0; o < 64; o += 4) {
            float4 wv = *reinterpret_cast<const float4*>(&s_w1t[i*64 + o]);
            h1[o+0] = fmaf(a, wv.x, h1[o+0]); h1[o+1] = fmaf(a, wv.y, h1[o+1]);
            h1[o+2] = fmaf(a, wv.z, h1[o+2]); h1[o+3] = fmaf(a, wv.w, h1[o+3]);
        }
    }
    #pragma unroll
    for (int o = 0; o < 64; o++) h1[o] = tanh_fast(h1[o]);

    // ---- layers 2+3 chunked: h2 chunk of 16 consumed immediately into y ----
    float y[16];
    #pragma unroll
    for (int o = 0; o < 16; o++) y[o] = s_b3[o];
    #pragma unroll
    for (int cch = 0; cch < 4; cch++) {
        float h2c[16];
        #pragma unroll
        for (int j = 0; j < 16; j++) h2c[j] = s_b2[cch*16 + j];
        #pragma unroll
        for (int i = 0; i < 64; i++) {
            float a = h1[i];
            #pragma unroll
            for (int j = 0; j < 16; j += 4) {
                float4 wv = *reinterpret_cast<const float4*>(&s_w2t[i*64 + cch*16 + j]);
                h2c[j+0] = fmaf(a, wv.x, h2c[j+0]); h2c[j+1] = fmaf(a, wv.y, h2c[j+1]);
                h2c[j+2] = fmaf(a, wv.z, h2c[j+2]); h2c[j+3] = fmaf(a, wv.w, h2c[j+3]);
            }
        }
        #pragma unroll
        for (int j = 0; j < 16; j++) {
            float a = tanh_fast(h2c[j]);
            int i = cch*16 + j;
            #pragma unroll
            for (int o = 0; o < 16; o += 4) {
                float4 wv = *reinterpret_cast<const float4*>(&s_w3t[i*16 + o]);
                y[o+0] = fmaf(a, wv.x, y[o+0]); y[o+1] = fmaf(a, wv.y, y[o+1]);
                y[o+2] = fmaf(a, wv.z, y[o+2]); y[o+3] = fmaf(a, wv.w, y[o+3]);
            }
        }
    }

    // ---- residual (re-read center from L2) + store ----
    float xn3 = 0.0f;
    #pragma unroll
    for (int c = 0; c < NC; c++) {
        float v = cur[c*VOL + pos] + y[c];
        g_B[c*VOL + pos] = v;
        if (c == 3) xn3 = v;
    }
    g_alive0[pos] = alive0v;

    // fused global-max of new ch3 (max(pool(f)) == max(f))
    float m = xn3;
    #pragma unroll
    for (int s = 16; s > 0; s >>= 1) m = fmaxf(m, __shfl_xor_sync(0xffffffffu, m, s));
    if ((tid & 31) == 0) s_wmax[tid >> 5] = m;
    __syncthreads();
    if (tid == 0) {
        float mm = s_wmax[0];
        #pragma unroll
        for (int i = 1; i < 6; i++) mm = fmaxf(mm, s_wmax[i]);
        atomicMax(&g_maxPost[step], encf(mm));
    }
}

// Masking + zero-slice; also reduces next step's pre-update global max of ch3.
__global__ __launch_bounds__(96) void finalize_kernel(
    float* __restrict__ out, int step, const int* __restrict__ pInOut)
{
    float* dst = (step == 3) ? out : (float*)g_A;

    int w = threadIdx.x, h = blockIdx.x, d = blockIdx.y;
    int pos = d*PLN + h*DD + w;

    bool vD[3] = { d > 0, true, d < DD-1 };
    bool vH[3] = { h > 0, true, h < DD-1 };
    bool vW[3] = { w > 0, true, w < DD-1 };
    const float* B3 = g_B + 3*VOL + pos;
    float m1 = -INFINITY;
    #pragma unroll
    for (int kd = 0; kd < 3; kd++)
        #pragma unroll
        for (int kh = 0; kh < 3; kh++)
            #pragma unroll
            for (int kw = 0; kw < 3; kw++)
                if (vD[kd] && vH[kh] && vW[kw])
                    m1 = fmaxf(m1, B3[(kd-1)*PLN + (kh-1)*DD + (kw-1)]);

    float th0 = 0.1f * decf(g_maxPre[step]);  if (isnan(th0)) th0 = -INFINITY;
    float th1 = 0.1f * decf(g_maxPost[step]); if (isnan(th1)) th1 = -INFINITY;
    bool life = (g_alive0[pos] > th0) && (m1 > th1);
    float lf = life ? 1.0f : 0.0f;
    bool zero = (d == DD-1) && (h >= *pInOut);

    float v3 = 0.0f;
    #pragma unroll
    for (int c = 0; c < NC; c++) {
        float v = g_B[c*VOL + pos] * lf;
        if (zero) v = 0.0f;
        dst[c*VOL + pos] = v;
        if (c == 3) v3 = v;
    }

    float m = v3;
    #pragma unroll
    for (int s = 16; s > 0; s >>= 1) m = fmaxf(m, __shfl_xor_sync(0xffffffffu, m, s));
    __shared__ float s_wmax[3];
    if ((threadIdx.x & 31) == 0) s_wmax[threadIdx.x >> 5] = m;
    __syncthreads();
    if (threadIdx.x == 0) {
        float mm = fmaxf(fmaxf(s_wmax[0], s_wmax[1]), s_wmax[2]);
        atomicMax(&g_maxPre[step + 1], encf(mm));
    }
}

extern "C" void kernel_launch(void* const* d_in, const int* in_sizes, int n_in,
                              void* d_out, int out_size) {
    (void)in_sizes; (void)n_in; (void)out_size;
    const float* x      = (const float*)d_in[0];
    const float* w_perc = (const float*)d_in[1];
    const float* b_perc = (const float*)d_in[2];
    const float* w1     = (const float*)d_in[3];
    const float* b1     = (const float*)d_in[4];
    const float* w2     = (const float*)d_in[5];
    const float* b2     = (const float*)d_in[6];
    const float* w3     = (const float*)d_in[7];
    const float* b3     = (const float*)d_in[8];
    const int*   pInOut = (const int*)d_in[12];
    float* out = (float*)d_out;

    init_kernel<<<1, 32>>>();
    reduce_ch3_kernel<<<432, 256>>>(x + 3*VOL);

    dim3 ublk(96, 2);
    dim3 ugrd(48, 96);
    dim3 fgrd(DD, DD);
    for (int s = 0; s < 4; s++) {
        update_kernel<<<ugrd, ublk>>>(x, w_perc, b_perc, w1, b1, w2, b2, w3, b3, s);
        finalize_kernel<<<fgrd, 96>>>(out, s, pInOut);
    }
}

// round 3
// speedup vs baseline: 2.4598x; 1.2757x over previous
#include <cuda_runtime.h>
#include <math.h>

#define DD  96
#define PLN (DD*DD)
#define VOL (DD*DD*DD)
#define NC  16

__device__ float    g_A[NC*VOL];
__device__ float    g_B[NC*VOL];
__device__ float    g_alive0[VOL];
__device__ unsigned g_maxPre[5];
__device__ unsigned g_maxPost[4];

__device__ __forceinline__ unsigned encf(float f) {
    unsigned u = __float_as_uint(f);
    return (u & 0x80000000u) ? ~u : (u | 0x80000000u);
}
__device__ __forceinline__ float decf(unsigned e) {
    return __uint_as_float((e & 0x80000000u) ? (e ^ 0x80000000u) : ~e);
}
__device__ __forceinline__ float tanh_fast(float x) {
    float y; asm("tanh.approx.f32 %0, %1;" : "=f"(y) : "f"(x)); return y;
}

// ---- packed f32x2 helpers (B300 FFMA2 path) ----
typedef unsigned long long u64t;
__device__ __forceinline__ u64t pack2(float lo, float hi) {
    u64t r; asm("mov.b64 %0, {%1, %2};" : "=l"(r) : "f"(lo), "f"(hi)); return r;
}
__device__ __forceinline__ void unpack2(u64t v, float& lo, float& hi) {
    asm("mov.b64 {%0, %1}, %2;" : "=f"(lo), "=f"(hi) : "l"(v));
}
__device__ __forceinline__ u64t ffma2(u64t a, u64t b, u64t c) {
    u64t d; asm("fma.rn.f32x2 %0, %1, %2, %3;" : "=l"(d) : "l"(a), "l"(b), "l"(c)); return d;
}

__global__ void init_kernel() {
    int t = threadIdx.x;
    if (t < 5) g_maxPre[t]  = 0x007FFFFFu;
    if (t < 4) g_maxPost[t] = 0x007FFFFFu;
}

__global__ void reduce_ch3_kernel(const float* __restrict__ p) {
    float m = -INFINITY;
    for (int i = blockIdx.x * blockDim.x + threadIdx.x; i < VOL; i += gridDim.x * blockDim.x)
        m = fmaxf(m, p[i]);
    #pragma unroll
    for (int s = 16; s > 0; s >>= 1) m = fmaxf(m, __shfl_xor_sync(0xffffffffu, m, s));
    __shared__ float sm[8];
    if ((threadIdx.x & 31) == 0) sm[threadIdx.x >> 5] = m;
    __syncthreads();
    if (threadIdx.x == 0) {
        int nw = (blockDim.x + 31) / 32;
        float mm = sm[0];
        for (int i = 1; i < nw; i++) mm = fmaxf(mm, sm[i]);
        atomicMax(&g_maxPre[0], encf(mm));
    }
}

// perm: logical conv output i = c*3+j  ->  scalar slot s = 2*((c/2)*3 + j) + (c%2)
__device__ __host__ __forceinline__ int perm48(int i) {
    int c = i / 3, j = i % 3;
    return 2 * ((c / 2) * 3 + j) + (c % 2);
}

__global__ __launch_bounds__(192, 2) void update_kernel(
    const float* __restrict__ xin,
    const float* __restrict__ w_perc, const float* __restrict__ b_perc,
    const float* __restrict__ w1, const float* __restrict__ b1,
    const float* __restrict__ w2, const float* __restrict__ b2,
    const float* __restrict__ w3, const float* __restrict__ b3,
    int step)
{
    const float* cur = (step == 0) ? xin : (const float*)g_A;

    // conv weight pairs: s_wpc[(c2*27 + k)*3 + j] = {w[(2c2)*3+j][k], w[(2c2+1)*3+j][k]}
    __shared__ u64t  s_wpc[8*27*3];
    __shared__ u64t  s_bpp[24];          // conv bias pairs in slot order
    __shared__ float s_w1t[48*64];       // [s(i)*64 + o]  (perm applied)
    __shared__ u64t  s_b1p[32];
    __shared__ float s_w2t[64*64];       // [i*64 + o]
    __shared__ u64t  s_b2p[32];
    __shared__ float s_w3t[64*16];       // [i*16 + o]
    __shared__ u64t  s_b3p[8];
    __shared__ float s_wmax[6];

    int tid = threadIdx.y * 96 + threadIdx.x;
    for (int idx = tid; idx < 8*27*3; idx += 192) {
        int c2 = idx / 81, r = idx % 81, k = r / 3, j = r % 3;
        float lo = w_perc[((2*c2)*3 + j)*27 + k];
        float hi = w_perc[((2*c2+1)*3 + j)*27 + k];
        s_wpc[idx] = pack2(lo, hi);
    }
    for (int idx = tid; idx < 48*64; idx += 192) {
        int o = idx / 48, i = idx % 48;
        s_w1t[perm48(i)*64 + o] = w1[idx];
    }
    for (int idx = tid; idx < 64*64; idx += 192) { int o = idx/64, i = idx%64; s_w2t[i*64 + o] = w2[idx]; }
    for (int idx = tid; idx < 16*64; idx += 192) { int o = idx/64, i = idx%64; s_w3t[i*16 + o] = w3[idx]; }
    if (tid < 24) { int p = tid, c2 = p/3, j = p%3;
        s_bpp[p] = pack2(b_perc[(2*c2)*3 + j], b_perc[(2*c2+1)*3 + j]); }
    else if (tid >= 32 && tid < 64) { int p = tid - 32; s_b1p[p] = pack2(b1[2*p], b1[2*p+1]); }
    else if (tid >= 64 && tid < 96) { int p = tid - 64; s_b2p[p] = pack2(b2[2*p], b2[2*p+1]); }
    else if (tid >= 96 && tid < 104) { int p = tid - 96; s_b3p[p] = pack2(b3[2*p], b3[2*p+1]); }
    __syncthreads();

    int w = threadIdx.x;
    int h = blockIdx.x * 2 + threadIdx.y;
    int d = blockIdx.y;
    int pos = d*PLN + h*DD + w;
    bool vD[3] = { d > 0, true, d < DD-1 };
    bool vH[3] = { h > 0, true, h < DD-1 };
    bool vW[3] = { w > 0, true, w < DD-1 };

    // ---- depthwise conv, channel-paired, FFMA2 ----
    u64t fp[24];
    #pragma unroll
    for (int p = 0; p < 24; p++) fp[p] = s_bpp[p];
    float alive0v = -INFINITY;

    #pragma unroll
    for (int c2 = 0; c2 < 8; c2++) {
        const float* b0 = cur + (2*c2)*VOL + pos;
        const float* b1p_ = b0 + VOL;
        #pragma unroll
        for (int kd = 0; kd < 3; kd++)
            #pragma unroll
            for (int kh = 0; kh < 3; kh++)
                #pragma unroll
                for (int kw = 0; kw < 3; kw++) {
                    int k = (kd*3 + kh)*3 + kw;
                    bool v = vD[kd] && vH[kh] && vW[kw];
                    int off = (kd-1)*PLN + (kh-1)*DD + (kw-1);
                    float v0 = v ? b0[off]   : 0.0f;
                    float v1 = v ? b1p_[off] : 0.0f;
                    if (c2 == 1 && v) alive0v = fmaxf(alive0v, v1);  // channel 3
                    u64t vp = pack2(v0, v1);
                    fp[c2*3+0] = ffma2(vp, s_wpc[(c2*27+k)*3+0], fp[c2*3+0]);
                    fp[c2*3+1] = ffma2(vp, s_wpc[(c2*27+k)*3+1], fp[c2*3+1]);
                    fp[c2*3+2] = ffma2(vp, s_wpc[(c2*27+k)*3+2], fp[c2*3+2]);
                }
    }

    // ---- layer 1: 48 -> 64 (pair outputs), tanh ----
    u64t h1p[32];
    #pragma unroll
    for (int p = 0; p < 32; p++) h1p[p] = s_b1p[p];
    #pragma unroll
    for (int p = 0; p < 24; p++) {
        float alo, ahi; unpack2(fp[p], alo, ahi);
        u64t aal = pack2(alo, alo), aah = pack2(ahi, ahi);
        int s0 = 2*p, s1 = 2*p + 1;
        #pragma unroll
        for (int o2 = 0; o2 < 32; o2 += 2) {
            ulonglong2 wv0 = *reinterpret_cast<const ulonglong2*>(&s_w1t[s0*64 + o2*2]);
            h1p[o2+0] = ffma2(aal, wv0.x, h1p[o2+0]);
            h1p[o2+1] = ffma2(aal, wv0.y, h1p[o2+1]);
        }
        #pragma unroll
        for (int o2 = 0; o2 < 32; o2 += 2) {
            ulonglong2 wv1 = *reinterpret_cast<const ulonglong2*>(&s_w1t[s1*64 + o2*2]);
            h1p[o2+0] = ffma2(aah, wv1.x, h1p[o2+0]);
            h1p[o2+1] = ffma2(aah, wv1.y, h1p[o2+1]);
        }
    }
    float h1s[64];
    #pragma unroll
    for (int p = 0; p < 32; p++) {
        float lo, hi; unpack2(h1p[p], lo, hi);
        h1s[2*p] = tanh_fast(lo); h1s[2*p+1] = tanh_fast(hi);
    }

    // ---- layer 2: 64 -> 64 (pair outputs) ----
    u64t h2p[32];
    #pragma unroll
    for (int p = 0; p < 32; p++) h2p[p] = s_b2p[p];
    #pragma unroll
    for (int i = 0; i < 64; i++) {
        float a = h1s[i];
        u64t aa = pack2(a, a);
        #pragma unroll
        for (int o2 = 0; o2 < 32; o2 += 2) {
            ulonglong2 wv = *reinterpret_cast<const ulonglong2*>(&s_w2t[i*64 + o2*2]);
            h2p[o2+0] = ffma2(aa, wv.x, h2p[o2+0]);
            h2p[o2+1] = ffma2(aa, wv.y, h2p[o2+1]);
        }
    }

    // ---- layer 3: 64 -> 16 (tanh fused on the fly) ----
    u64t yp[8];
    #pragma unroll
    for (int p = 0; p < 8; p++) yp[p] = s_b3p[p];
    #pragma unroll
    for (int p = 0; p < 32; p++) {
        float lo, hi; unpack2(h2p[p], lo, hi);
        float tl = tanh_fast(lo), th = tanh_fast(hi);
        u64t aal = pack2(tl, tl), aah = pack2(th, th);
        int i0 = 2*p, i1 = 2*p + 1;
        #pragma unroll
        for (int o2 = 0; o2 < 8; o2 += 2) {
            ulonglong2 wv = *reinterpret_cast<const ulonglong2*>(&s_w3t[i0*16 + o2*2]);
            yp[o2+0] = ffma2(aal, wv.x, yp[o2+0]);
            yp[o2+1] = ffma2(aal, wv.y, yp[o2+1]);
        }
        #pragma unroll
        for (int o2 = 0; o2 < 8; o2 += 2) {
            ulonglong2 wv = *reinterpret_cast<const ulonglong2*>(&s_w3t[i1*16 + o2*2]);
            yp[o2+0] = ffma2(aal = aah, wv.x, yp[o2+0]);
            yp[o2+1] = ffma2(aah, wv.y, yp[o2+1]);
        }
    }

    // ---- residual + store ----
    float xn3 = 0.0f;
    #pragma unroll
    for (int p = 0; p < 8; p++) {
        float ylo, yhi; unpack2(yp[p], ylo, yhi);
        int c0 = 2*p, c1 = 2*p + 1;
        float v0 = cur[c0*VOL + pos] + ylo;
        float v1 = cur[c1*VOL + pos] + yhi;
        g_B[c0*VOL + pos] = v0;
        g_B[c1*VOL + pos] = v1;
        if (p == 1) xn3 = v1;  // channel 3
    }
    g_alive0[pos] = alive0v;

    float m = xn3;
    #pragma unroll
    for (int s = 16; s > 0; s >>= 1) m = fmaxf(m, __shfl_xor_sync(0xffffffffu, m, s));
    if ((tid & 31) == 0) s_wmax[tid >> 5] = m;
    __syncthreads();
    if (tid == 0) {
        float mm = s_wmax[0];
        #pragma unroll
        for (int i = 1; i < 6; i++) mm = fmaxf(mm, s_wmax[i]);
        atomicMax(&g_maxPost[step], encf(mm));
    }
}

__global__ __launch_bounds__(96) void finalize_kernel(
    float* __restrict__ out, int step, const int* __restrict__ pInOut)
{
    float* dst = (step == 3) ? out : (float*)g_A;

    int w = threadIdx.x, h = blockIdx.x, d = blockIdx.y;
    int pos = d*PLN + h*DD + w;

    bool vD[3] = { d > 0, true, d < DD-1 };
    bool vH[3] = { h > 0, true, h < DD-1 };
    bool vW[3] = { w > 0, true, w < DD-1 };
    const float* B3 = g_B + 3*VOL + pos;
    float m1 = -INFINITY;
    #pragma unroll
    for (int kd = 0; kd < 3; kd++)
        #pragma unroll
        for (int kh = 0; kh < 3; kh++)
            #pragma unroll
            for (int kw = 0; kw < 3; kw++)
                if (vD[kd] && vH[kh] && vW[kw])
                    m1 = fmaxf(m1, B3[(kd-1)*PLN + (kh-1)*DD + (kw-1)]);

    float th0 = 0.1f * decf(g_maxPre[step]);  if (isnan(th0)) th0 = -INFINITY;
    float th1 = 0.1f * decf(g_maxPost[step]); if (isnan(th1)) th1 = -INFINITY;
    bool life = (g_alive0[pos] > th0) && (m1 > th1);
    float lf = life ? 1.0f : 0.0f;
    bool zero = (d == DD-1) && (h >= *pInOut);

    float v3 = 0.0f;
    #pragma unroll
    for (int c = 0; c < NC; c++) {
        float v = g_B[c*VOL + pos] * lf;
        if (zero) v = 0.0f;
        dst[c*VOL + pos] = v;
        if (c == 3) v3 = v;
    }

    float m = v3;
    #pragma unroll
    for (int s = 16; s > 0; s >>= 1) m = fmaxf(m, __shfl_xor_sync(0xffffffffu, m, s));
    __shared__ float s_wmax[3];
    if ((threadIdx.x & 31) == 0) s_wmax[threadIdx.x >> 5] = m;
    __syncthreads();
    if (threadIdx.x == 0) {
        float mm = fmaxf(fmaxf(s_wmax[0], s_wmax[1]), s_wmax[2]);
        atomicMax(&g_maxPre[step + 1], encf(mm));
    }
}

extern "C" void kernel_launch(void* const* d_in, const int* in_sizes, int n_in,
                              void* d_out, int out_size) {
    (void)in_sizes; (void)n_in; (void)out_size;
    const float* x      = (const float*)d_in[0];
    const float* w_perc = (const float*)d_in[1];
    const float* b_perc = (const float*)d_in[2];
    const float* w1     = (const float*)d_in[3];
    const float* b1     = (const float*)d_in[4];
    const float* w2     = (const float*)d_in[5];
    const float* b2     = (const float*)d_in[6];
    const float* w3     = (const float*)d_in[7];
    const float* b3     = (const float*)d_in[8];
    const int*   pInOut = (const int*)d_in[12];
    float* out = (float*)d_out;

    init_kernel<<<1, 32>>>();
    reduce_ch3_kernel<<<432, 256>>>(x + 3*VOL);

    dim3 ublk(96, 2);
    dim3 ugrd(48, 96);
    dim3 fgrd(DD, DD);
    for (int s = 0; s < 4; s++) {
        update_kernel<<<ugrd, ublk>>>(x, w_perc, b_perc, w1, b1, w2, b2, w3, b3, s);
        finalize_kernel<<<fgrd, 96>>>(out, s, pInOut);
    }
}